// round 10
// baseline (speedup 1.0000x reference)
#include <cuda_runtime.h>
#include <cstdint>

// VTBPR fused kernel (R10): smem-staged output + one 32KB async bulk store
// per CTA (cp.async.bulk.global.shared::cta -> UBLKCP).
//   score[b] = item_beta[i] + user_beta[u] + <ug,ig> + <tv,vf_b> + <tt,tf_b>
//   metapath[b,0,p,l,:] = ug if path_type==0, ig if ==1, else 0
//
// d_out = [ score (B floats) | metapath (B*16*512 floats) ]
//
// R10 theory: R2..R9 falsified occupancy, store order, CTA batching, and
// every L2 policy (.cs/.wt writes, .cs/evict_last reads) -- all land at
// 56-58us ncu, DRAM ~69% with 31% idle cycles on a 268MB-write mix.
// Remaining suspect: DRAM burst/turnaround efficiency of 2048 interleaved
// STG.128 per CTA. Replace with ONE contiguous 32KB bulk store per CTA via
// the async-proxy path: larger ordered bursts at the DRAM controller.

#define HIDDEN 512
#define VEC    (HIDDEN / 4)   // 128 float4 lanes
#define PL     16             // P*L
#define TILE_BYTES (PL * HIDDEN * 4)   // 32768 per batch row

__device__ __forceinline__ uint32_t smem_u32(const void* p) {
    uint32_t a;
    asm("{ .reg .u64 t; cvta.to.shared.u64 t, %1; cvt.u32.u64 %0, t; }"
        : "=r"(a) : "l"(p));
    return a;
}

__global__ void __launch_bounds__(VEC)
vtbpr_kernel(const float* __restrict__ user_gama,
             const float* __restrict__ item_gama,
             const float* __restrict__ user_beta,
             const float* __restrict__ item_beta,
             const float* __restrict__ theta_user_visual,
             const float* __restrict__ theta_user_text,
             const float* __restrict__ visual_features,
             const float* __restrict__ textural_features,
             const int*   __restrict__ user_idx,
             const int*   __restrict__ item_idx,
             const int*   __restrict__ path_type,
             float* __restrict__ out,
             int B)
{
    const int b   = blockIdx.x;
    const int tid = threadIdx.x;           // 0..127

    __shared__ __align__(128) float4 stage[PL * VEC];   // 32 KB output tile
    __shared__ int   pt[PL];
    __shared__ float wsum[VEC / 32];

    const int u = user_idx[b];
    const int i = item_idx[b];

    if (tid < PL) pt[tid] = path_type[b * PL + tid];

    const float4* ug_p = (const float4*)(user_gama         + (size_t)u * HIDDEN);
    const float4* ig_p = (const float4*)(item_gama         + (size_t)i * HIDDEN);
    const float4* tv_p = (const float4*)(theta_user_visual + (size_t)u * HIDDEN);
    const float4* tt_p = (const float4*)(theta_user_text   + (size_t)u * HIDDEN);
    const float4* vf_p = (const float4*)(visual_features   + (size_t)b * HIDDEN);
    const float4* tf_p = (const float4*)(textural_features + (size_t)b * HIDDEN);

    // Front-batch all six loads (max MLP).
    const float4 ug4 = ug_p[tid];
    const float4 ig4 = ig_p[tid];
    const float4 tv4 = tv_p[tid];
    const float4 tt4 = tt_p[tid];
    const float4 vf4 = vf_p[tid];
    const float4 tf4 = tf_p[tid];

    __syncthreads();   // orders pt STS (arrives with LDGs in flight)

    // Build the 32KB output tile in smem (conflict-free: 16B stride lanes).
    const float4 zero4 = make_float4(0.f, 0.f, 0.f, 0.f);
    #pragma unroll
    for (int j = 0; j < PL; j++) {
        const int t = pt[j];
        stage[j * VEC + tid] = (t == 0) ? ug4 : ((t == 1) ? ig4 : zero4);
    }

    // Dot products + warp reduce (overlaps the STS above)
    float partial =
        ug4.x * ig4.x + ug4.y * ig4.y + ug4.z * ig4.z + ug4.w * ig4.w +
        tv4.x * vf4.x + tv4.y * vf4.y + tv4.z * vf4.z + tv4.w * vf4.w +
        tt4.x * tf4.x + tt4.y * tf4.y + tt4.z * tf4.z + tt4.w * tf4.w;

    #pragma unroll
    for (int off = 16; off > 0; off >>= 1)
        partial += __shfl_xor_sync(0xFFFFFFFFu, partial, off);

    if ((tid & 31) == 0) wsum[tid >> 5] = partial;
    __syncthreads();   // stage[] and wsum[] complete

    if (tid == 0) {
        float s = user_beta[u] + item_beta[i];
        #pragma unroll
        for (int w = 0; w < VEC / 32; w++) s += wsum[w];
        out[b] = s;

        // One contiguous 32KB bulk store: smem tile -> metapath[b]
        asm volatile("fence.proxy.async.shared::cta;" ::: "memory");
        float* dst = out + B + (size_t)b * PL * HIDDEN;
        uint32_t src = smem_u32(stage);
        asm volatile(
            "cp.async.bulk.global.shared::cta.bulk_group [%0], [%1], %2;"
            :: "l"(dst), "r"(src), "r"((uint32_t)TILE_BYTES) : "memory");
        asm volatile("cp.async.bulk.commit_group;" ::: "memory");
        asm volatile("cp.async.bulk.wait_group 0;" ::: "memory");
    }
}

extern "C" void kernel_launch(void* const* d_in, const int* in_sizes, int n_in,
                              void* d_out, int out_size)
{
    const float* user_gama          = (const float*)d_in[0];
    const float* item_gama          = (const float*)d_in[1];
    const float* user_beta          = (const float*)d_in[2];
    const float* item_beta          = (const float*)d_in[3];
    const float* theta_user_visual  = (const float*)d_in[4];
    const float* theta_user_text    = (const float*)d_in[5];
    const float* visual_features    = (const float*)d_in[6];
    const float* textural_features  = (const float*)d_in[7];
    const int*   user_idx           = (const int*)d_in[8];
    const int*   item_idx           = (const int*)d_in[9];
    const int*   path_type          = (const int*)d_in[10];

    const int B = in_sizes[8];  // 8192

    vtbpr_kernel<<<B, VEC>>>(user_gama, item_gama, user_beta, item_beta,
                             theta_user_visual, theta_user_text,
                             visual_features, textural_features,
                             user_idx, item_idx, path_type,
                             (float*)d_out, B);
}

// round 11
// speedup vs baseline: 1.0083x; 1.0083x over previous
#include <cuda_runtime.h>
#include <cstdint>

// VTBPR fused kernel (R11): consolidation round.
//   score[b] = item_beta[i] + user_beta[u] + <ug,ig> + <tv,vf_b> + <tt,tf_b>
//   metapath[b,0,p,l,:] = ug if path_type==0, ig if ==1, else 0
//
// d_out = [ score (B floats) | metapath (B*16*512 floats) ]
//
// Established across R2-R10: ~5.5TB/s is the DRAM ceiling for this
// 268MB-write/42MB-read mix -- invariant to occupancy (26%..88%), store
// path (STG vs UBLKCP), L2 policy (.cs/.wt/evict_last), store ordering,
// and CTA batching. R11 keeps the best-measured base (R9) and removes the
// last fixed costs:
//   - 2 rows per 256-thread CTA (4096 CTAs): halves per-CTA overhead,
//     rows run in parallel in disjoint half-blocks (no serialization,
//     no register growth -- unlike R5).
//   - beta loads hoisted so the score tail has no dependent LDG chain.
//   - evict_last retained on vector reads (best-of-band in R9).

#define HIDDEN 512
#define VEC    (HIDDEN / 4)   // 128 float4 lanes per row
#define PL     16             // P*L
#define NT     256            // threads per CTA (2 rows)

__device__ __forceinline__ uint64_t policy_evict_last() {
    uint64_t p;
    asm("createpolicy.fractional.L2::evict_last.b64 %0, 1.0;" : "=l"(p));
    return p;
}

__device__ __forceinline__ float4 ld_el(const float4* a, uint64_t pol) {
    float4 v;
    asm("ld.global.L2::cache_hint.v4.f32 {%0,%1,%2,%3}, [%4], %5;"
        : "=f"(v.x), "=f"(v.y), "=f"(v.z), "=f"(v.w)
        : "l"(a), "l"(pol));
    return v;
}

__global__ void __launch_bounds__(NT, 4)
vtbpr_kernel(const float* __restrict__ user_gama,
             const float* __restrict__ item_gama,
             const float* __restrict__ user_beta,
             const float* __restrict__ item_beta,
             const float* __restrict__ theta_user_visual,
             const float* __restrict__ theta_user_text,
             const float* __restrict__ visual_features,
             const float* __restrict__ textural_features,
             const int*   __restrict__ user_idx,
             const int*   __restrict__ item_idx,
             const int*   __restrict__ path_type,
             float* __restrict__ out,
             int B)
{
    const int tid  = threadIdx.x;          // 0..255
    const int half = tid >> 7;             // which row this half-block owns
    const int lane = tid & (VEC - 1);      // 0..127 within the row
    const int b    = blockIdx.x * 2 + half;

    __shared__ int   pt[2][PL];
    __shared__ float wsum[2][VEC / 32];

    const int u = user_idx[b];
    const int i = item_idx[b];

    // Stage both rows' path types (first 32 threads), hoist beta loads.
    if (tid < 2 * PL) pt[tid >> 4][tid & 15] = path_type[blockIdx.x * 2 * PL + tid];
    const float ub = user_beta[u];
    const float ib = item_beta[i];

    const uint64_t pol = policy_evict_last();

    const float4* ug_p = (const float4*)(user_gama         + (size_t)u * HIDDEN);
    const float4* ig_p = (const float4*)(item_gama         + (size_t)i * HIDDEN);
    const float4* tv_p = (const float4*)(theta_user_visual + (size_t)u * HIDDEN);
    const float4* tt_p = (const float4*)(theta_user_text   + (size_t)u * HIDDEN);
    const float4* vf_p = (const float4*)(visual_features   + (size_t)b * HIDDEN);
    const float4* tf_p = (const float4*)(textural_features + (size_t)b * HIDDEN);

    // Front-batch all six vector loads (max MLP), pinned evict_last in L2.
    const float4 ug4 = ld_el(&ug_p[lane], pol);
    const float4 ig4 = ld_el(&ig_p[lane], pol);
    const float4 tv4 = ld_el(&tv_p[lane], pol);
    const float4 tt4 = ld_el(&tt_p[lane], pol);
    const float4 vf4 = ld_el(&vf_p[lane], pol);
    const float4 tf4 = ld_el(&tf_p[lane], pol);

    // Dot products + warp reduce
    float partial =
        ug4.x * ig4.x + ug4.y * ig4.y + ug4.z * ig4.z + ug4.w * ig4.w +
        tv4.x * vf4.x + tv4.y * vf4.y + tv4.z * vf4.z + tv4.w * vf4.w +
        tt4.x * tf4.x + tt4.y * tf4.y + tt4.z * tf4.z + tt4.w * tf4.w;

    #pragma unroll
    for (int off = 16; off > 0; off >>= 1)
        partial += __shfl_xor_sync(0xFFFFFFFFu, partial, off);

    if ((tid & 31) == 0) wsum[half][(tid >> 5) & 3] = partial;
    __syncthreads();   // orders pt STS + wsum

    if ((tid & (VEC - 1)) == 0) {
        float s = ub + ib;
        #pragma unroll
        for (int w = 0; w < VEC / 32; w++) s += wsum[half][w];
        out[b] = s;
    }

    // Metapath scatter: 16 coalesced STG.128 per thread per row.
    float4* mp = (float4*)(out + B + (size_t)b * PL * HIDDEN);
    const float4 zero4 = make_float4(0.f, 0.f, 0.f, 0.f);

    #pragma unroll
    for (int j = 0; j < PL; j++) {
        const int t = pt[half][j];
        const float4 v = (t == 0) ? ug4 : ((t == 1) ? ig4 : zero4);
        mp[(size_t)j * VEC + lane] = v;
    }
}

extern "C" void kernel_launch(void* const* d_in, const int* in_sizes, int n_in,
                              void* d_out, int out_size)
{
    const float* user_gama          = (const float*)d_in[0];
    const float* item_gama          = (const float*)d_in[1];
    const float* user_beta          = (const float*)d_in[2];
    const float* item_beta          = (const float*)d_in[3];
    const float* theta_user_visual  = (const float*)d_in[4];
    const float* theta_user_text    = (const float*)d_in[5];
    const float* visual_features    = (const float*)d_in[6];
    const float* textural_features  = (const float*)d_in[7];
    const int*   user_idx           = (const int*)d_in[8];
    const int*   item_idx           = (const int*)d_in[9];
    const int*   path_type          = (const int*)d_in[10];

    const int B = in_sizes[8];  // 8192 (even)

    vtbpr_kernel<<<B / 2, NT>>>(user_gama, item_gama, user_beta, item_beta,
                                theta_user_visual, theta_user_text,
                                visual_features, textural_features,
                                user_idx, item_idx, path_type,
                                (float*)d_out, B);
}